// round 1
// baseline (speedup 1.0000x reference)
#include <cuda_runtime.h>
#include <cuda_bf16.h>
#include <math.h>

// Problem constants
#define BB 2
#define TT 2048
#define DD 1024
#define HH 16
#define HD 64
#define MM (BB*TT)   // 4096

// Scratch (device globals: allocation-free)
__device__ float g_qh[BB*HH*TT*HD];   // [B,H,T,hd]
__device__ float g_kh[BB*HH*TT*HD];
__device__ float g_vh[BB*HH*TT*HD];
__device__ float g_attn[BB*TT*DD];    // [B,T,D]

// ---------------------------------------------------------------------------
// GEMM: C[m][n] = sum_k A[m][k] * W[n][k] + bias[n]
// A: [M,K] row-major, W: [N,K] row-major (i.e. X @ W^T + b, torch Linear)
// headMode==1: write to [B,H,T,hd] layout (b=m>>11, t=m&2047, h=n>>6, d=n&63)
// Tiling: 128x128 block, K-step 8, 256 threads, 8x8 per-thread microtile.
// ---------------------------------------------------------------------------
__global__ void __launch_bounds__(256) gemm_kernel(
    const float* __restrict__ A, const float* __restrict__ W,
    const float* __restrict__ bias, float* __restrict__ C,
    int M, int N, int K, int headMode)
{
    __shared__ float As[8][132];
    __shared__ float Ws[8][132];

    const int tid = threadIdx.x;
    const int bm = blockIdx.y * 128;
    const int bn = blockIdx.x * 128;
    const int lr = tid >> 1;           // 0..127 row within tile
    const int lc = (tid & 1) * 4;      // k offset 0 or 4
    const int tm = (tid >> 4) * 8;     // microtile row
    const int tn = (tid & 15) * 8;     // microtile col

    const float* Ap = A + (size_t)(bm + lr) * K + lc;
    const float* Wp = W + (size_t)(bn + lr) * K + lc;

    float acc[8][8];
#pragma unroll
    for (int i = 0; i < 8; i++)
#pragma unroll
        for (int j = 0; j < 8; j++) acc[i][j] = 0.f;

    for (int kt = 0; kt < K; kt += 8) {
        float4 a = *(const float4*)(Ap + kt);
        float4 w = *(const float4*)(Wp + kt);
        __syncthreads();
        As[lc + 0][lr] = a.x; As[lc + 1][lr] = a.y;
        As[lc + 2][lr] = a.z; As[lc + 3][lr] = a.w;
        Ws[lc + 0][lr] = w.x; Ws[lc + 1][lr] = w.y;
        Ws[lc + 2][lr] = w.z; Ws[lc + 3][lr] = w.w;
        __syncthreads();
#pragma unroll
        for (int kk = 0; kk < 8; kk++) {
            float4 a0 = *(const float4*)&As[kk][tm];
            float4 a1 = *(const float4*)&As[kk][tm + 4];
            float4 w0 = *(const float4*)&Ws[kk][tn];
            float4 w1 = *(const float4*)&Ws[kk][tn + 4];
            float av[8] = {a0.x, a0.y, a0.z, a0.w, a1.x, a1.y, a1.z, a1.w};
            float wv[8] = {w0.x, w0.y, w0.z, w0.w, w1.x, w1.y, w1.z, w1.w};
#pragma unroll
            for (int i = 0; i < 8; i++)
#pragma unroll
                for (int j = 0; j < 8; j++)
                    acc[i][j] += av[i] * wv[j];
        }
    }

    if (headMode == 0) {
#pragma unroll
        for (int i = 0; i < 8; i++) {
            int m = bm + tm + i;
            float* cp = C + (size_t)m * N + bn + tn;
#pragma unroll
            for (int j = 0; j < 8; j += 4) {
                float4 o;
                o.x = acc[i][j + 0] + bias[bn + tn + j + 0];
                o.y = acc[i][j + 1] + bias[bn + tn + j + 1];
                o.z = acc[i][j + 2] + bias[bn + tn + j + 2];
                o.w = acc[i][j + 3] + bias[bn + tn + j + 3];
                *(float4*)(cp + j) = o;
            }
        }
    } else {
#pragma unroll
        for (int i = 0; i < 8; i++) {
            int m = bm + tm + i;
            int b = m >> 11;          // m / 2048
            int t = m & 2047;
#pragma unroll
            for (int j = 0; j < 8; j++) {
                int n = bn + tn + j;
                int h = n >> 6;
                int d = n & 63;
                C[(((size_t)b * HH + h) * TT + t) * HD + d] = acc[i][j] + bias[n];
            }
        }
    }
}

// ---------------------------------------------------------------------------
// Flash attention (fp32), Br=Bc=64, hd=64. One block per (b,h,q-tile).
// Smem layouts (all padded stride 68):
//   Qs[d][q]  (Q transposed, pre-scaled by 1/sqrt(hd))
//   Ks[d][k]  (K transposed)
//   Vs[k][d]
//   Ps[k][q]  (softmax probs transposed)
// 256 threads = 16x16 grid of 4x4 microtiles. Row stats reduced via
// 16-lane xor-shuffles (lanes of a row group are contiguous within a warp).
// ---------------------------------------------------------------------------
#define FPAD 68
#define FSMEM (4 * 64 * FPAD * (int)sizeof(float))  // 69632 bytes

__global__ void __launch_bounds__(256) flash_kernel(
    const float* __restrict__ Qh, const float* __restrict__ Kh,
    const float* __restrict__ Vh, float* __restrict__ Out)
{
    extern __shared__ float sm[];
    float* Qs = sm;
    float* Ks = Qs + 64 * FPAD;
    float* Vs = Ks + 64 * FPAD;
    float* Ps = Vs + 64 * FPAD;

    const int qt = blockIdx.x;   // 0..31
    const int h  = blockIdx.y;   // 0..15
    const int b  = blockIdx.z;   // 0..1
    const int tid = threadIdx.x;
    const int tx = tid & 15;
    const int ty = tid >> 4;
    const int r0 = ty * 4;       // query rows owned
    const int c0 = tx * 4;       // key/d cols owned

    const float scale = 0.125f;  // 1/sqrt(64)
    const float* Qg = Qh + (((size_t)b * HH + h) * TT + qt * 64) * HD;
    const float* Kb = Kh + (((size_t)b * HH + h) * TT) * HD;
    const float* Vb = Vh + (((size_t)b * HH + h) * TT) * HD;

    // Load Q tile transposed, pre-scaled
#pragma unroll
    for (int i = 0; i < 4; i++) {
        int lin = tid + i * 256;      // float4 index (1024 total)
        int q = lin >> 4;
        int d = (lin & 15) * 4;
        float4 v = *(const float4*)(Qg + q * HD + d);
        Qs[(d + 0) * FPAD + q] = v.x * scale;
        Qs[(d + 1) * FPAD + q] = v.y * scale;
        Qs[(d + 2) * FPAD + q] = v.z * scale;
        Qs[(d + 3) * FPAD + q] = v.w * scale;
    }

    float acc[4][4];
    float mi[4], li[4];
#pragma unroll
    for (int i = 0; i < 4; i++) {
        mi[i] = -1e30f; li[i] = 0.f;
#pragma unroll
        for (int j = 0; j < 4; j++) acc[i][j] = 0.f;
    }

    for (int jt = 0; jt < TT / 64; ++jt) {
        __syncthreads();   // guard Ks/Vs/Ps reuse from previous iteration
        const float* Kg = Kb + jt * 64 * HD;
        const float* Vg = Vb + jt * 64 * HD;
#pragma unroll
        for (int i = 0; i < 4; i++) {
            int lin = tid + i * 256;
            int r = lin >> 4;
            int d = (lin & 15) * 4;
            float4 kv = *(const float4*)(Kg + r * HD + d);
            Ks[(d + 0) * FPAD + r] = kv.x;
            Ks[(d + 1) * FPAD + r] = kv.y;
            Ks[(d + 2) * FPAD + r] = kv.z;
            Ks[(d + 3) * FPAD + r] = kv.w;
            float4 vv = *(const float4*)(Vg + r * HD + d);
            *(float4*)(Vs + r * FPAD + d) = vv;
        }
        __syncthreads();

        // S = Q @ K^T (scale already folded into Q)
        float s[4][4];
#pragma unroll
        for (int i = 0; i < 4; i++)
#pragma unroll
            for (int j = 0; j < 4; j++) s[i][j] = 0.f;

#pragma unroll 8
        for (int d = 0; d < 64; d++) {
            float4 qv = *(const float4*)(Qs + d * FPAD + r0);
            float4 kv = *(const float4*)(Ks + d * FPAD + c0);
            float qa[4] = {qv.x, qv.y, qv.z, qv.w};
            float ka[4] = {kv.x, kv.y, kv.z, kv.w};
#pragma unroll
            for (int i = 0; i < 4; i++)
#pragma unroll
                for (int j = 0; j < 4; j++)
                    s[i][j] += qa[i] * ka[j];
        }

        // Online softmax per query row
#pragma unroll
        for (int i = 0; i < 4; i++) {
            float rm = fmaxf(fmaxf(s[i][0], s[i][1]), fmaxf(s[i][2], s[i][3]));
#pragma unroll
            for (int off = 8; off; off >>= 1)
                rm = fmaxf(rm, __shfl_xor_sync(0xffffffffu, rm, off));
            float nm = fmaxf(mi[i], rm);
            float corr = __expf(mi[i] - nm);
            mi[i] = nm;
            float rs = 0.f;
#pragma unroll
            for (int j = 0; j < 4; j++) {
                s[i][j] = __expf(s[i][j] - nm);
                rs += s[i][j];
            }
#pragma unroll
            for (int off = 8; off; off >>= 1)
                rs += __shfl_xor_sync(0xffffffffu, rs, off);
            li[i] = li[i] * corr + rs;
#pragma unroll
            for (int j = 0; j < 4; j++) acc[i][j] *= corr;
        }

        // Write P transposed: Ps[k][q]
#pragma unroll
        for (int i = 0; i < 4; i++)
#pragma unroll
            for (int j = 0; j < 4; j++)
                Ps[(c0 + j) * FPAD + (r0 + i)] = s[i][j];
        __syncthreads();

        // O += P @ V
#pragma unroll 8
        for (int k = 0; k < 64; k++) {
            float4 pv = *(const float4*)(Ps + k * FPAD + r0);
            float4 vv = *(const float4*)(Vs + k * FPAD + c0);
            float pa[4] = {pv.x, pv.y, pv.z, pv.w};
            float va[4] = {vv.x, vv.y, vv.z, vv.w};
#pragma unroll
            for (int i = 0; i < 4; i++)
#pragma unroll
                for (int j = 0; j < 4; j++)
                    acc[i][j] += pa[i] * va[j];
        }
    }

    // Epilogue: Out[b][t][h*64 + d] = acc / l
#pragma unroll
    for (int i = 0; i < 4; i++) {
        float inv = 1.f / li[i];
        int t = qt * 64 + r0 + i;
        float4 o;
        o.x = acc[i][0] * inv;
        o.y = acc[i][1] * inv;
        o.z = acc[i][2] * inv;
        o.w = acc[i][3] * inv;
        *(float4*)(Out + ((size_t)b * TT + t) * DD + h * HD + c0) = o;
    }
}

// ---------------------------------------------------------------------------
extern "C" void kernel_launch(void* const* d_in, const int* in_sizes, int n_in,
                              void* d_out, int out_size)
{
    const float* q  = (const float*)d_in[0];
    const float* k  = (const float*)d_in[1];
    const float* v  = (const float*)d_in[2];
    const float* Wq = (const float*)d_in[3];
    const float* bq = (const float*)d_in[4];
    const float* Wk = (const float*)d_in[5];
    const float* bk = (const float*)d_in[6];
    const float* Wv = (const float*)d_in[7];
    const float* bv = (const float*)d_in[8];
    const float* Wo = (const float*)d_in[9];
    const float* bo = (const float*)d_in[10];
    float* out = (float*)d_out;

    float *qh, *kh, *vh, *attn;
    cudaGetSymbolAddress((void**)&qh,   g_qh);
    cudaGetSymbolAddress((void**)&kh,   g_kh);
    cudaGetSymbolAddress((void**)&vh,   g_vh);
    cudaGetSymbolAddress((void**)&attn, g_attn);

    dim3 ggrid(DD / 128, MM / 128);   // (8, 32)

    // Input projections -> head layout
    gemm_kernel<<<ggrid, 256>>>(q, Wq, bq, qh, MM, DD, DD, 1);
    gemm_kernel<<<ggrid, 256>>>(k, Wk, bk, kh, MM, DD, DD, 1);
    gemm_kernel<<<ggrid, 256>>>(v, Wv, bv, vh, MM, DD, DD, 1);

    // Flash attention -> [B,T,D]
    cudaFuncSetAttribute(flash_kernel,
                         cudaFuncAttributeMaxDynamicSharedMemorySize, FSMEM);
    dim3 fgrid(TT / 64, HH, BB);      // (32, 16, 2)
    flash_kernel<<<fgrid, 256, FSMEM>>>(qh, kh, vh, attn);

    // Output projection -> d_out
    gemm_kernel<<<ggrid, 256>>>(attn, Wo, bo, out, MM, DD, DD, 0);
}

// round 3
// speedup vs baseline: 1.4782x; 1.4782x over previous
#include <cuda_runtime.h>
#include <cuda_bf16.h>
#include <cstdint>
#include <math.h>

// Problem constants
#define BB 2
#define TT 2048
#define DD 1024
#define HH 16
#define HD 64
#define MM (BB*TT)   // 4096

// Scratch (device globals: allocation-free)
__device__ float g_qh[BB*HH*TT*HD];   // [B,H,T,hd]
__device__ float g_kh[BB*HH*TT*HD];
__device__ float g_vh[BB*HH*TT*HD];
__device__ float g_attn[BB*TT*DD];    // [B,T,D]

// ===========================================================================
// Helpers
// ===========================================================================
__device__ __forceinline__ uint32_t smem_u32(const void* p) {
    uint32_t a;
    asm("{ .reg .u64 t; cvta.to.shared.u64 t, %1; cvt.u32.u64 %0, t; }"
        : "=r"(a) : "l"(p));
    return a;
}

__device__ __forceinline__ void cp_async16(uint32_t dst, const void* src) {
    asm volatile("cp.async.cg.shared.global [%0], [%1], 16;\n"
                 :: "r"(dst), "l"(src));
}

__device__ __forceinline__ uint32_t f2tf32(float x) {
    uint32_t r;
    asm("cvt.rna.tf32.f32 %0, %1;" : "=r"(r) : "f"(x));
    return r;
}

__device__ __forceinline__ void mma_tf32(float* c, const uint32_t* a,
                                         const uint32_t* b) {
    asm volatile(
        "mma.sync.aligned.m16n8k8.row.col.f32.tf32.tf32.f32 "
        "{%0,%1,%2,%3}, {%4,%5,%6,%7}, {%8,%9}, {%0,%1,%2,%3};\n"
        : "+f"(c[0]), "+f"(c[1]), "+f"(c[2]), "+f"(c[3])
        : "r"(a[0]), "r"(a[1]), "r"(a[2]), "r"(a[3]),
          "r"(b[0]), "r"(b[1]));
}

// ===========================================================================
// tf32 mma.sync GEMM: C[m][n] = sum_k A[m][k]*W[n][k] + bias[n]
// A [M,1024], W [1024,1024], both K-major. Block tile 128x128, 8 warps,
// warp tile 32x64 (2x8 m16n8k8), K-chunk 16, double-buffered cp.async.
// Smem stride 20 floats -> fragment LDS hits all 32 banks (conflict-free).
// headMode==1: C written to [B,H,T,hd] layout.
// ===========================================================================
#define KC 16
#define ST 20

__global__ void __launch_bounds__(256) gemm_tc_kernel(
    const float* __restrict__ A, const float* __restrict__ W,
    const float* __restrict__ bias, float* __restrict__ C, int headMode)
{
    __shared__ float As[2][128 * ST];
    __shared__ float Bs[2][128 * ST];

    const int tid = threadIdx.x;
    const int wid = tid >> 5;
    const int lane = tid & 31;
    const int g = lane >> 2;      // groupID
    const int t = lane & 3;       // threadID in group
    const int bm = blockIdx.y * 128;
    const int bn = blockIdx.x * 128;
    const int wm = (wid & 3) * 32;   // warp m offset in tile
    const int wn = (wid >> 2) * 64;  // warp n offset in tile

    const uint32_t aB = smem_u32(As);
    const uint32_t bB = smem_u32(Bs);
    const int lrow = tid >> 2;       // load row 0..63 (x2 via i loop)
    const int lseg = tid & 3;        // 16B segment 0..3

    float acc[2][8][4];
#pragma unroll
    for (int mt = 0; mt < 2; mt++)
#pragma unroll
        for (int nt = 0; nt < 8; nt++)
#pragma unroll
            for (int i = 0; i < 4; i++) acc[mt][nt][i] = 0.f;

    const int NC = DD / KC;   // 64

    // ---- load chunk c into stage s ----
    auto issue = [&](int c, int s) {
#pragma unroll
        for (int i = 0; i < 2; i++) {
            int row = lrow + i * 64;
            uint32_t soff = (uint32_t)(s * 128 * ST + row * ST + lseg * 4) * 4;
            const float* ag = A + (size_t)(bm + row) * DD + c * KC + lseg * 4;
            const float* wg = W + (size_t)(bn + row) * DD + c * KC + lseg * 4;
            cp_async16(aB + soff, ag);
            cp_async16(bB + soff, wg);
        }
        asm volatile("cp.async.commit_group;\n" ::: "memory");
    };

    issue(0, 0);

    for (int c = 0; c < NC; c++) {
        int s = c & 1;
        if (c + 1 < NC) issue(c + 1, s ^ 1);

        if (c + 1 < NC) asm volatile("cp.async.wait_group 1;\n" ::: "memory");
        else            asm volatile("cp.async.wait_group 0;\n" ::: "memory");
        __syncthreads();

        const float* as = As[s];
        const float* bs = Bs[s];
#pragma unroll
        for (int ks = 0; ks < 2; ks++) {
            const int k0 = ks * 8;
            uint32_t af[2][4];
            uint32_t bf[8][2];
#pragma unroll
            for (int mt = 0; mt < 2; mt++) {
                int r = wm + mt * 16 + g;
                af[mt][0] = f2tf32(as[r * ST + k0 + t]);
                af[mt][1] = f2tf32(as[(r + 8) * ST + k0 + t]);
                af[mt][2] = f2tf32(as[r * ST + k0 + t + 4]);
                af[mt][3] = f2tf32(as[(r + 8) * ST + k0 + t + 4]);
            }
#pragma unroll
            for (int nt = 0; nt < 8; nt++) {
                int rn = wn + nt * 8 + g;
                bf[nt][0] = f2tf32(bs[rn * ST + k0 + t]);
                bf[nt][1] = f2tf32(bs[rn * ST + k0 + t + 4]);
            }
#pragma unroll
            for (int mt = 0; mt < 2; mt++)
#pragma unroll
                for (int nt = 0; nt < 8; nt++)
                    mma_tf32(acc[mt][nt], af[mt], bf[nt]);
        }
        __syncthreads();
    }

    // ---- epilogue: fragment -> global, bias added, optional head layout ----
#pragma unroll
    for (int mt = 0; mt < 2; mt++) {
#pragma unroll
        for (int nt = 0; nt < 8; nt++) {
            int m0 = bm + wm + mt * 16 + g;
            int n0 = bn + wn + nt * 8 + 2 * t;
            float b0 = bias[n0];
            float b1 = bias[n0 + 1];
            float2 r0 = make_float2(acc[mt][nt][0] + b0, acc[mt][nt][1] + b1);
            float2 r1 = make_float2(acc[mt][nt][2] + b0, acc[mt][nt][3] + b1);
            if (headMode == 0) {
                *(float2*)(C + (size_t)m0 * DD + n0) = r0;
                *(float2*)(C + (size_t)(m0 + 8) * DD + n0) = r1;
            } else {
                int h = n0 >> 6, d = n0 & 63;
                int b = m0 >> 11, tt0 = m0 & 2047;
                *(float2*)(C + (((size_t)b * HH + h) * TT + tt0) * HD + d) = r0;
                *(float2*)(C + (((size_t)b * HH + h) * TT + tt0 + 8) * HD + d) = r1;
            }
        }
    }
}

// ---------------------------------------------------------------------------
// Flash attention (fp32), Br=Bc=64, hd=64. One block per (b,h,q-tile).
// (unchanged — fp32 SIMT; next optimization target)
// ---------------------------------------------------------------------------
#define FPAD 68
#define FSMEM (4 * 64 * FPAD * (int)sizeof(float))  // 69632 bytes

__global__ void __launch_bounds__(256) flash_kernel(
    const float* __restrict__ Qh, const float* __restrict__ Kh,
    const float* __restrict__ Vh, float* __restrict__ Out)
{
    extern __shared__ float sm[];
    float* Qs = sm;
    float* Ks = Qs + 64 * FPAD;
    float* Vs = Ks + 64 * FPAD;
    float* Ps = Vs + 64 * FPAD;

    const int qt = blockIdx.x;
    const int h  = blockIdx.y;
    const int b  = blockIdx.z;
    const int tid = threadIdx.x;
    const int tx = tid & 15;
    const int ty = tid >> 4;
    const int r0 = ty * 4;
    const int c0 = tx * 4;

    const float scale = 0.125f;
    const float* Qg = Qh + (((size_t)b * HH + h) * TT + qt * 64) * HD;
    const float* Kb = Kh + (((size_t)b * HH + h) * TT) * HD;
    const float* Vb = Vh + (((size_t)b * HH + h) * TT) * HD;

#pragma unroll
    for (int i = 0; i < 4; i++) {
        int lin = tid + i * 256;
        int q = lin >> 4;
        int d = (lin & 15) * 4;
        float4 v = *(const float4*)(Qg + q * HD + d);
        Qs[(d + 0) * FPAD + q] = v.x * scale;
        Qs[(d + 1) * FPAD + q] = v.y * scale;
        Qs[(d + 2) * FPAD + q] = v.z * scale;
        Qs[(d + 3) * FPAD + q] = v.w * scale;
    }

    float acc[4][4];
    float mi[4], li[4];
#pragma unroll
    for (int i = 0; i < 4; i++) {
        mi[i] = -1e30f; li[i] = 0.f;
#pragma unroll
        for (int j = 0; j < 4; j++) acc[i][j] = 0.f;
    }

    for (int jt = 0; jt < TT / 64; ++jt) {
        __syncthreads();
        const float* Kg = Kb + jt * 64 * HD;
        const float* Vg = Vb + jt * 64 * HD;
#pragma unroll
        for (int i = 0; i < 4; i++) {
            int lin = tid + i * 256;
            int r = lin >> 4;
            int d = (lin & 15) * 4;
            float4 kv = *(const float4*)(Kg + r * HD + d);
            Ks[(d + 0) * FPAD + r] = kv.x;
            Ks[(d + 1) * FPAD + r] = kv.y;
            Ks[(d + 2) * FPAD + r] = kv.z;
            Ks[(d + 3) * FPAD + r] = kv.w;
            float4 vv = *(const float4*)(Vg + r * HD + d);
            *(float4*)(Vs + r * FPAD + d) = vv;
        }
        __syncthreads();

        float s[4][4];
#pragma unroll
        for (int i = 0; i < 4; i++)
#pragma unroll
            for (int j = 0; j < 4; j++) s[i][j] = 0.f;

#pragma unroll 8
        for (int d = 0; d < 64; d++) {
            float4 qv = *(const float4*)(Qs + d * FPAD + r0);
            float4 kv = *(const float4*)(Ks + d * FPAD + c0);
            float qa[4] = {qv.x, qv.y, qv.z, qv.w};
            float ka[4] = {kv.x, kv.y, kv.z, kv.w};
#pragma unroll
            for (int i = 0; i < 4; i++)
#pragma unroll
                for (int j = 0; j < 4; j++)
                    s[i][j] += qa[i] * ka[j];
        }

#pragma unroll
        for (int i = 0; i < 4; i++) {
            float rm = fmaxf(fmaxf(s[i][0], s[i][1]), fmaxf(s[i][2], s[i][3]));
#pragma unroll
            for (int off = 8; off; off >>= 1)
                rm = fmaxf(rm, __shfl_xor_sync(0xffffffffu, rm, off));
            float nm = fmaxf(mi[i], rm);
            float corr = __expf(mi[i] - nm);
            mi[i] = nm;
            float rs = 0.f;
#pragma unroll
            for (int j = 0; j < 4; j++) {
                s[i][j] = __expf(s[i][j] - nm);
                rs += s[i][j];
            }
#pragma unroll
            for (int off = 8; off; off >>= 1)
                rs += __shfl_xor_sync(0xffffffffu, rs, off);
            li[i] = li[i] * corr + rs;
#pragma unroll
            for (int j = 0; j < 4; j++) acc[i][j] *= corr;
        }

#pragma unroll
        for (int i = 0; i < 4; i++)
#pragma unroll
            for (int j = 0; j < 4; j++)
                Ps[(c0 + j) * FPAD + (r0 + i)] = s[i][j];
        __syncthreads();

#pragma unroll 8
        for (int k = 0; k < 64; k++) {
            float4 pv = *(const float4*)(Ps + k * FPAD + r0);
            float4 vv = *(const float4*)(Vs + k * FPAD + c0);
            float pa[4] = {pv.x, pv.y, pv.z, pv.w};
            float va[4] = {vv.x, vv.y, vv.z, vv.w};
#pragma unroll
            for (int i = 0; i < 4; i++)
#pragma unroll
                for (int j = 0; j < 4; j++)
                    acc[i][j] += pa[i] * va[j];
        }
    }

#pragma unroll
    for (int i = 0; i < 4; i++) {
        float inv = 1.f / li[i];
        int t = qt * 64 + r0 + i;
        float4 o;
        o.x = acc[i][0] * inv;
        o.y = acc[i][1] * inv;
        o.z = acc[i][2] * inv;
        o.w = acc[i][3] * inv;
        *(float4*)(Out + ((size_t)b * TT + t) * DD + h * HD + c0) = o;
    }
}

// ---------------------------------------------------------------------------
extern "C" void kernel_launch(void* const* d_in, const int* in_sizes, int n_in,
                              void* d_out, int out_size)
{
    const float* q  = (const float*)d_in[0];
    const float* k  = (const float*)d_in[1];
    const float* v  = (const float*)d_in[2];
    const float* Wq = (const float*)d_in[3];
    const float* bq = (const float*)d_in[4];
    const float* Wk = (const float*)d_in[5];
    const float* bk = (const float*)d_in[6];
    const float* Wv = (const float*)d_in[7];
    const float* bv = (const float*)d_in[8];
    const float* Wo = (const float*)d_in[9];
    const float* bo = (const float*)d_in[10];
    float* out = (float*)d_out;

    float *qh, *kh, *vh, *attn;
    cudaGetSymbolAddress((void**)&qh,   g_qh);
    cudaGetSymbolAddress((void**)&kh,   g_kh);
    cudaGetSymbolAddress((void**)&vh,   g_vh);
    cudaGetSymbolAddress((void**)&attn, g_attn);

    cudaFuncSetAttribute(flash_kernel,
                         cudaFuncAttributeMaxDynamicSharedMemorySize, FSMEM);

    dim3 ggrid(DD / 128, MM / 128);   // (8, 32)

    gemm_tc_kernel<<<ggrid, 256>>>(q, Wq, bq, qh, 1);
    gemm_tc_kernel<<<ggrid, 256>>>(k, Wk, bk, kh, 1);
    gemm_tc_kernel<<<ggrid, 256>>>(v, Wv, bv, vh, 1);

    dim3 fgrid(TT / 64, HH, BB);      // (32, 16, 2)
    flash_kernel<<<fgrid, 256, FSMEM>>>(qh, kh, vh, attn);

    gemm_tc_kernel<<<ggrid, 256>>>(attn, Wo, bo, out, 0);
}

// round 4
// speedup vs baseline: 2.6214x; 1.7734x over previous
#include <cuda_runtime.h>
#include <cuda_bf16.h>
#include <cstdint>
#include <math.h>

// Problem constants
#define BB 2
#define TT 2048
#define DD 1024
#define HH 16
#define HD 64
#define MM (BB*TT)   // 4096

// Scratch (device globals: allocation-free)
__device__ float g_qh[BB*HH*TT*HD];   // [B,H,T,hd]
__device__ float g_kh[BB*HH*TT*HD];
__device__ float g_vh[BB*HH*TT*HD];
__device__ float g_attn[BB*TT*DD];    // [B,T,D]

// ===========================================================================
// Helpers
// ===========================================================================
__device__ __forceinline__ uint32_t smem_u32(const void* p) {
    uint32_t a;
    asm("{ .reg .u64 t; cvta.to.shared.u64 t, %1; cvt.u32.u64 %0, t; }"
        : "=r"(a) : "l"(p));
    return a;
}

__device__ __forceinline__ void cp_async16(uint32_t dst, const void* src) {
    asm volatile("cp.async.cg.shared.global [%0], [%1], 16;\n"
                 :: "r"(dst), "l"(src));
}

__device__ __forceinline__ uint32_t f2tf32(float x) {
    uint32_t r;
    asm("cvt.rna.tf32.f32 %0, %1;" : "=r"(r) : "f"(x));
    return r;
}

__device__ __forceinline__ void mma_tf32(float* c, const uint32_t* a,
                                         const uint32_t* b) {
    asm volatile(
        "mma.sync.aligned.m16n8k8.row.col.f32.tf32.tf32.f32 "
        "{%0,%1,%2,%3}, {%4,%5,%6,%7}, {%8,%9}, {%0,%1,%2,%3};\n"
        : "+f"(c[0]), "+f"(c[1]), "+f"(c[2]), "+f"(c[3])
        : "r"(a[0]), "r"(a[1]), "r"(a[2]), "r"(a[3]),
          "r"(b[0]), "r"(b[1]));
}

__device__ __forceinline__ void mma_bf16(float* c, const uint32_t* a,
                                         const uint32_t* b) {
    asm volatile(
        "mma.sync.aligned.m16n8k16.row.col.f32.bf16.bf16.f32 "
        "{%0,%1,%2,%3}, {%4,%5,%6,%7}, {%8,%9}, {%0,%1,%2,%3};\n"
        : "+f"(c[0]), "+f"(c[1]), "+f"(c[2]), "+f"(c[3])
        : "r"(a[0]), "r"(a[1]), "r"(a[2]), "r"(a[3]),
          "r"(b[0]), "r"(b[1]));
}

// Split (x,y) into hi/lo bf16x2 words (low half = x).
__device__ __forceinline__ void split2(float x, float y,
                                       uint32_t& hi, uint32_t& lo) {
    __nv_bfloat16 hx = __float2bfloat16(x);
    __nv_bfloat16 hy = __float2bfloat16(y);
    __nv_bfloat16 lx = __float2bfloat16(x - __bfloat162float(hx));
    __nv_bfloat16 ly = __float2bfloat16(y - __bfloat162float(hy));
    __nv_bfloat162 ph = __halves2bfloat162(hx, hy);
    __nv_bfloat162 pl = __halves2bfloat162(lx, ly);
    hi = *(uint32_t*)&ph;
    lo = *(uint32_t*)&pl;
}

// ===========================================================================
// tf32 mma.sync GEMM (unchanged from round 3): C = A @ W^T + bias
// ===========================================================================
#define KC 16
#define ST 20

__global__ void __launch_bounds__(256) gemm_tc_kernel(
    const float* __restrict__ A, const float* __restrict__ W,
    const float* __restrict__ bias, float* __restrict__ C, int headMode)
{
    __shared__ float As[2][128 * ST];
    __shared__ float Bs[2][128 * ST];

    const int tid = threadIdx.x;
    const int wid = tid >> 5;
    const int lane = tid & 31;
    const int g = lane >> 2;
    const int t = lane & 3;
    const int bm = blockIdx.y * 128;
    const int bn = blockIdx.x * 128;
    const int wm = (wid & 3) * 32;
    const int wn = (wid >> 2) * 64;

    const uint32_t aB = smem_u32(As);
    const uint32_t bB = smem_u32(Bs);
    const int lrow = tid >> 2;
    const int lseg = tid & 3;

    float acc[2][8][4];
#pragma unroll
    for (int mt = 0; mt < 2; mt++)
#pragma unroll
        for (int nt = 0; nt < 8; nt++)
#pragma unroll
            for (int i = 0; i < 4; i++) acc[mt][nt][i] = 0.f;

    const int NC = DD / KC;   // 64

    auto issue = [&](int c, int s) {
#pragma unroll
        for (int i = 0; i < 2; i++) {
            int row = lrow + i * 64;
            uint32_t soff = (uint32_t)(s * 128 * ST + row * ST + lseg * 4) * 4;
            const float* ag = A + (size_t)(bm + row) * DD + c * KC + lseg * 4;
            const float* wg = W + (size_t)(bn + row) * DD + c * KC + lseg * 4;
            cp_async16(aB + soff, ag);
            cp_async16(bB + soff, wg);
        }
        asm volatile("cp.async.commit_group;\n" ::: "memory");
    };

    issue(0, 0);

    for (int c = 0; c < NC; c++) {
        int s = c & 1;
        if (c + 1 < NC) issue(c + 1, s ^ 1);

        if (c + 1 < NC) asm volatile("cp.async.wait_group 1;\n" ::: "memory");
        else            asm volatile("cp.async.wait_group 0;\n" ::: "memory");
        __syncthreads();

        const float* as = As[s];
        const float* bs = Bs[s];
#pragma unroll
        for (int ks = 0; ks < 2; ks++) {
            const int k0 = ks * 8;
            uint32_t af[2][4];
            uint32_t bf[8][2];
#pragma unroll
            for (int mt = 0; mt < 2; mt++) {
                int r = wm + mt * 16 + g;
                af[mt][0] = f2tf32(as[r * ST + k0 + t]);
                af[mt][1] = f2tf32(as[(r + 8) * ST + k0 + t]);
                af[mt][2] = f2tf32(as[r * ST + k0 + t + 4]);
                af[mt][3] = f2tf32(as[(r + 8) * ST + k0 + t + 4]);
            }
#pragma unroll
            for (int nt = 0; nt < 8; nt++) {
                int rn = wn + nt * 8 + g;
                bf[nt][0] = f2tf32(bs[rn * ST + k0 + t]);
                bf[nt][1] = f2tf32(bs[rn * ST + k0 + t + 4]);
            }
#pragma unroll
            for (int mt = 0; mt < 2; mt++)
#pragma unroll
                for (int nt = 0; nt < 8; nt++)
                    mma_tf32(acc[mt][nt], af[mt], bf[nt]);
        }
        __syncthreads();
    }

#pragma unroll
    for (int mt = 0; mt < 2; mt++) {
#pragma unroll
        for (int nt = 0; nt < 8; nt++) {
            int m0 = bm + wm + mt * 16 + g;
            int n0 = bn + wn + nt * 8 + 2 * t;
            float b0 = bias[n0];
            float b1 = bias[n0 + 1];
            float2 r0 = make_float2(acc[mt][nt][0] + b0, acc[mt][nt][1] + b1);
            float2 r1 = make_float2(acc[mt][nt][2] + b0, acc[mt][nt][3] + b1);
            if (headMode == 0) {
                *(float2*)(C + (size_t)m0 * DD + n0) = r0;
                *(float2*)(C + (size_t)(m0 + 8) * DD + n0) = r1;
            } else {
                int h = n0 >> 6, d = n0 & 63;
                int b = m0 >> 11, tt0 = m0 & 2047;
                *(float2*)(C + (((size_t)b * HH + h) * TT + tt0) * HD + d) = r0;
                *(float2*)(C + (((size_t)b * HH + h) * TT + tt0 + 8) * HD + d) = r1;
            }
        }
    }
}

// ===========================================================================
// Flash attention via split-bf16 mma.sync.  Br=128, Bc=64, 8 warps.
// Each warp owns m16 x n64 of S, so P C-frags map directly onto PV A-frags.
// Smem: hi/lo bf16x2 words, row stride 36 words -> conflict-free frag LDS.
// Error ~1e-5 (16-bit effective mantissa via 3-term products).
// ===========================================================================
#define FW 36
#define FQH 0
#define FQL 4608
#define FKH 9216
#define FKL 11520
#define FVH 13824
#define FVL 16128
#define FLASH_SMEM (18432 * 4)   // 73728 bytes

__global__ void __launch_bounds__(256) flash_tc_kernel(
    const float* __restrict__ Qp, const float* __restrict__ Kp,
    const float* __restrict__ Vp, float* __restrict__ Out)
{
    extern __shared__ uint32_t sm[];
    uint32_t* sQH = sm + FQH;
    uint32_t* sQL = sm + FQL;
    uint32_t* sKH = sm + FKH;
    uint32_t* sKL = sm + FKL;
    uint32_t* sVH = sm + FVH;
    uint32_t* sVL = sm + FVL;

    const int tid = threadIdx.x;
    const int wid = tid >> 5;
    const int lane = tid & 31;
    const int g = lane >> 2;
    const int t = lane & 3;
    const int qt = blockIdx.x;   // 0..15
    const int h  = blockIdx.y;
    const int b  = blockIdx.z;

    const float* Qg = Qp + (((size_t)b * HH + h) * TT + qt * 128) * HD;
    const float* Kg = Kp + (((size_t)b * HH + h) * TT) * HD;
    const float* Vg = Vp + (((size_t)b * HH + h) * TT) * HD;

    // ---- load Q once, pre-scaled by 1/sqrt(hd) ----
#pragma unroll
    for (int it = 0; it < 8; it++) {
        int lin = tid + it * 256;
        int row = lin >> 4;
        int seg = lin & 15;
        float4 v = *(const float4*)(Qg + row * HD + seg * 4);
        v.x *= 0.125f; v.y *= 0.125f; v.z *= 0.125f; v.w *= 0.125f;
        uint32_t h0, l0, h1, l1;
        split2(v.x, v.y, h0, l0);
        split2(v.z, v.w, h1, l1);
        sQH[row * FW + seg * 2]     = h0;
        sQH[row * FW + seg * 2 + 1] = h1;
        sQL[row * FW + seg * 2]     = l0;
        sQL[row * FW + seg * 2 + 1] = l1;
    }

    float o[8][4];
#pragma unroll
    for (int j = 0; j < 8; j++)
#pragma unroll
        for (int i = 0; i < 4; i++) o[j][i] = 0.f;
    float mi0 = -1e30f, mi1 = -1e30f, li0 = 0.f, li1 = 0.f;

    const int mq = wid * 16;

    for (int jt = 0; jt < TT / 64; jt++) {
        __syncthreads();   // previous tile fully consumed (also covers Q load)
        // ---- K tile ----
#pragma unroll
        for (int it = 0; it < 4; it++) {
            int lin = tid + it * 256;
            int row = lin >> 4;
            int seg = lin & 15;
            float4 v = *(const float4*)(Kg + (size_t)(jt * 64 + row) * HD + seg * 4);
            uint32_t h0, l0, h1, l1;
            split2(v.x, v.y, h0, l0);
            split2(v.z, v.w, h1, l1);
            sKH[row * FW + seg * 2]     = h0;
            sKH[row * FW + seg * 2 + 1] = h1;
            sKL[row * FW + seg * 2]     = l0;
            sKL[row * FW + seg * 2 + 1] = l1;
        }
        // ---- V tile, transposed: sV[hd][key-pair] ----
#pragma unroll
        for (int it = 0; it < 4; it++) {
            int lin = tid + it * 256;
            int r = lin & 31;        // key pair index
            int c = lin >> 5;        // hd col pair 0..31
            const float* vp = Vg + (size_t)(jt * 64 + 2 * r) * HD + 2 * c;
            float2 v0 = *(const float2*)vp;
            float2 v1 = *(const float2*)(vp + HD);
            uint32_t h0, l0, h1, l1;
            split2(v0.x, v1.x, h0, l0);   // keys 2r, 2r+1 at hd col 2c
            split2(v0.y, v1.y, h1, l1);   // at hd col 2c+1
            sVH[(2 * c) * FW + r]     = h0;
            sVH[(2 * c + 1) * FW + r] = h1;
            sVL[(2 * c) * FW + r]     = l0;
            sVL[(2 * c + 1) * FW + r] = l1;
        }
        __syncthreads();

        // ---- S = Qs @ K^T  (split-bf16, 3 products) ----
        float sc[8][4];
#pragma unroll
        for (int j = 0; j < 8; j++)
#pragma unroll
            for (int i = 0; i < 4; i++) sc[j][i] = 0.f;

#pragma unroll
        for (int kb = 0; kb < 4; kb++) {
            int ab = (mq + g) * FW + kb * 8 + t;
            uint32_t aH[4] = { sQH[ab], sQH[ab + 8 * FW],
                               sQH[ab + 4], sQH[ab + 8 * FW + 4] };
            uint32_t aL[4] = { sQL[ab], sQL[ab + 8 * FW],
                               sQL[ab + 4], sQL[ab + 8 * FW + 4] };
#pragma unroll
            for (int j = 0; j < 8; j++) {
                int bb = (8 * j + g) * FW + kb * 8 + t;
                uint32_t bH[2] = { sKH[bb], sKH[bb + 4] };
                uint32_t bL[2] = { sKL[bb], sKL[bb + 4] };
                mma_bf16(sc[j], aH, bH);
                mma_bf16(sc[j], aH, bL);
                mma_bf16(sc[j], aL, bH);
            }
        }

        // ---- online softmax (rows g and g+8 of this warp's 16) ----
        float m0 = -1e30f, m1 = -1e30f;
#pragma unroll
        for (int j = 0; j < 8; j++) {
            m0 = fmaxf(m0, fmaxf(sc[j][0], sc[j][1]));
            m1 = fmaxf(m1, fmaxf(sc[j][2], sc[j][3]));
        }
        m0 = fmaxf(m0, __shfl_xor_sync(0xffffffffu, m0, 1));
        m0 = fmaxf(m0, __shfl_xor_sync(0xffffffffu, m0, 2));
        m1 = fmaxf(m1, __shfl_xor_sync(0xffffffffu, m1, 1));
        m1 = fmaxf(m1, __shfl_xor_sync(0xffffffffu, m1, 2));

        float nm0 = fmaxf(mi0, m0), nm1 = fmaxf(mi1, m1);
        float cr0 = __expf(mi0 - nm0), cr1 = __expf(mi1 - nm1);
        mi0 = nm0; mi1 = nm1;

        float rs0 = 0.f, rs1 = 0.f;
#pragma unroll
        for (int j = 0; j < 8; j++) {
            sc[j][0] = __expf(sc[j][0] - nm0);
            sc[j][1] = __expf(sc[j][1] - nm0);
            sc[j][2] = __expf(sc[j][2] - nm1);
            sc[j][3] = __expf(sc[j][3] - nm1);
            rs0 += sc[j][0] + sc[j][1];
            rs1 += sc[j][2] + sc[j][3];
        }
        rs0 += __shfl_xor_sync(0xffffffffu, rs0, 1);
        rs0 += __shfl_xor_sync(0xffffffffu, rs0, 2);
        rs1 += __shfl_xor_sync(0xffffffffu, rs1, 1);
        rs1 += __shfl_xor_sync(0xffffffffu, rs1, 2);
        li0 = li0 * cr0 + rs0;
        li1 = li1 * cr1 + rs1;

#pragma unroll
        for (int j = 0; j < 8; j++) {
            o[j][0] *= cr0; o[j][1] *= cr0;
            o[j][2] *= cr1; o[j][3] *= cr1;
        }

        // ---- O += P @ V  (split-bf16, P frags directly from S frags) ----
#pragma unroll
        for (int kb = 0; kb < 4; kb++) {
            uint32_t aH[4], aL[4];
            split2(sc[2 * kb][0],     sc[2 * kb][1],     aH[0], aL[0]);
            split2(sc[2 * kb][2],     sc[2 * kb][3],     aH[1], aL[1]);
            split2(sc[2 * kb + 1][0], sc[2 * kb + 1][1], aH[2], aL[2]);
            split2(sc[2 * kb + 1][2], sc[2 * kb + 1][3], aH[3], aL[3]);
#pragma unroll
            for (int j = 0; j < 8; j++) {
                int vb = (8 * j + g) * FW + kb * 8 + t;
                uint32_t bH[2] = { sVH[vb], sVH[vb + 4] };
                uint32_t bL[2] = { sVL[vb], sVL[vb + 4] };
                mma_bf16(o[j], aH, bH);
                mma_bf16(o[j], aH, bL);
                mma_bf16(o[j], aL, bH);
            }
        }
    }

    // ---- epilogue: normalize, write [B,T,D] ----
    float inv0 = 1.f / li0, inv1 = 1.f / li1;
    int row0 = qt * 128 + mq + g;
#pragma unroll
    for (int j = 0; j < 8; j++) {
        int col = h * HD + j * 8 + 2 * t;
        float2 r0 = make_float2(o[j][0] * inv0, o[j][1] * inv0);
        float2 r1 = make_float2(o[j][2] * inv1, o[j][3] * inv1);
        *(float2*)(Out + ((size_t)b * TT + row0) * DD + col) = r0;
        *(float2*)(Out + ((size_t)b * TT + row0 + 8) * DD + col) = r1;
    }
}

// ---------------------------------------------------------------------------
extern "C" void kernel_launch(void* const* d_in, const int* in_sizes, int n_in,
                              void* d_out, int out_size)
{
    const float* q  = (const float*)d_in[0];
    const float* k  = (const float*)d_in[1];
    const float* v  = (const float*)d_in[2];
    const float* Wq = (const float*)d_in[3];
    const float* bq = (const float*)d_in[4];
    const float* Wk = (const float*)d_in[5];
    const float* bk = (const float*)d_in[6];
    const float* Wv = (const float*)d_in[7];
    const float* bv = (const float*)d_in[8];
    const float* Wo = (const float*)d_in[9];
    const float* bo = (const float*)d_in[10];
    float* out = (float*)d_out;

    float *qh, *kh, *vh, *attn;
    cudaGetSymbolAddress((void**)&qh,   g_qh);
    cudaGetSymbolAddress((void**)&kh,   g_kh);
    cudaGetSymbolAddress((void**)&vh,   g_vh);
    cudaGetSymbolAddress((void**)&attn, g_attn);

    cudaFuncSetAttribute(flash_tc_kernel,
                         cudaFuncAttributeMaxDynamicSharedMemorySize, FLASH_SMEM);

    dim3 ggrid(DD / 128, MM / 128);   // (8, 32)

    gemm_tc_kernel<<<ggrid, 256>>>(q, Wq, bq, qh, 1);
    gemm_tc_kernel<<<ggrid, 256>>>(k, Wk, bk, kh, 1);
    gemm_tc_kernel<<<ggrid, 256>>>(v, Wv, bv, vh, 1);

    dim3 fgrid(TT / 128, HH, BB);     // (16, 16, 2)
    flash_tc_kernel<<<fgrid, 256, FLASH_SMEM>>>(qh, kh, vh, attn);

    gemm_tc_kernel<<<ggrid, 256>>>(attn, Wo, bo, out, 0);
}

// round 5
// speedup vs baseline: 3.1534x; 1.2029x over previous
#include <cuda_runtime.h>
#include <cuda_bf16.h>
#include <cstdint>
#include <math.h>

// Problem constants
#define BB 2
#define TT 2048
#define DD 1024
#define HH 16
#define HD 64
#define MM (BB*TT)   // 4096

// Scratch (device globals: allocation-free)
__device__ float g_qh[BB*HH*TT*HD];   // [B,H,T,hd]
__device__ float g_kh[BB*HH*TT*HD];
__device__ float g_vh[BB*HH*TT*HD];
__device__ float g_attn[BB*TT*DD];    // [B,T,D]

// ===========================================================================
// Helpers
// ===========================================================================
__device__ __forceinline__ uint32_t smem_u32(const void* p) {
    uint32_t a;
    asm("{ .reg .u64 t; cvta.to.shared.u64 t, %1; cvt.u32.u64 %0, t; }"
        : "=r"(a) : "l"(p));
    return a;
}

__device__ __forceinline__ void cp_async16(uint32_t dst, const void* src) {
    asm volatile("cp.async.cg.shared.global [%0], [%1], 16;\n"
                 :: "r"(dst), "l"(src));
}

__device__ __forceinline__ uint32_t f2tf32(float x) {
    uint32_t r;
    asm("cvt.rna.tf32.f32 %0, %1;" : "=r"(r) : "f"(x));
    return r;
}

__device__ __forceinline__ void mma_tf32(float* c, const uint32_t* a,
                                         const uint32_t* b) {
    asm volatile(
        "mma.sync.aligned.m16n8k8.row.col.f32.tf32.tf32.f32 "
        "{%0,%1,%2,%3}, {%4,%5,%6,%7}, {%8,%9}, {%0,%1,%2,%3};\n"
        : "+f"(c[0]), "+f"(c[1]), "+f"(c[2]), "+f"(c[3])
        : "r"(a[0]), "r"(a[1]), "r"(a[2]), "r"(a[3]),
          "r"(b[0]), "r"(b[1]));
}

__device__ __forceinline__ void mma_bf16(float* c, const uint32_t* a,
                                         const uint32_t* b) {
    asm volatile(
        "mma.sync.aligned.m16n8k16.row.col.f32.bf16.bf16.f32 "
        "{%0,%1,%2,%3}, {%4,%5,%6,%7}, {%8,%9}, {%0,%1,%2,%3};\n"
        : "+f"(c[0]), "+f"(c[1]), "+f"(c[2]), "+f"(c[3])
        : "r"(a[0]), "r"(a[1]), "r"(a[2]), "r"(a[3]),
          "r"(b[0]), "r"(b[1]));
}

__device__ __forceinline__ void ldsm4(uint32_t* r, uint32_t addr) {
    asm volatile(
        "ldmatrix.sync.aligned.m8n8.x4.shared.b16 {%0,%1,%2,%3}, [%4];"
        : "=r"(r[0]), "=r"(r[1]), "=r"(r[2]), "=r"(r[3]) : "r"(addr));
}

__device__ __forceinline__ void ldsm4t(uint32_t* r, uint32_t addr) {
    asm volatile(
        "ldmatrix.sync.aligned.m8n8.x4.trans.shared.b16 {%0,%1,%2,%3}, [%4];"
        : "=r"(r[0]), "=r"(r[1]), "=r"(r[2]), "=r"(r[3]) : "r"(addr));
}

// Split (x,y) into hi/lo bf16x2 words (low half = x).
__device__ __forceinline__ void split2(float x, float y,
                                       uint32_t& hi, uint32_t& lo) {
    __nv_bfloat16 hx = __float2bfloat16(x);
    __nv_bfloat16 hy = __float2bfloat16(y);
    __nv_bfloat16 lx = __float2bfloat16(x - __bfloat162float(hx));
    __nv_bfloat16 ly = __float2bfloat16(y - __bfloat162float(hy));
    __nv_bfloat162 ph = __halves2bfloat162(hx, hy);
    __nv_bfloat162 pl = __halves2bfloat162(lx, ly);
    hi = *(uint32_t*)&ph;
    lo = *(uint32_t*)&pl;
}

// ===========================================================================
// tf32 mma.sync GEMM body (round-3 proven): C = A @ W^T + bias
// ===========================================================================
#define KC 16
#define ST 20

__device__ __forceinline__ void gemm_body(
    const float* __restrict__ A, const float* __restrict__ W,
    const float* __restrict__ bias, float* __restrict__ C, int headMode,
    float* As, float* Bs)
{
    const int tid = threadIdx.x;
    const int wid = tid >> 5;
    const int lane = tid & 31;
    const int g = lane >> 2;
    const int t = lane & 3;
    const int bm = blockIdx.y * 128;
    const int bn = blockIdx.x * 128;
    const int wm = (wid & 3) * 32;
    const int wn = (wid >> 2) * 64;

    const uint32_t aB = smem_u32(As);
    const uint32_t bB = smem_u32(Bs);
    const int lrow = tid >> 2;
    const int lseg = tid & 3;

    float acc[2][8][4];
#pragma unroll
    for (int mt = 0; mt < 2; mt++)
#pragma unroll
        for (int nt = 0; nt < 8; nt++)
#pragma unroll
            for (int i = 0; i < 4; i++) acc[mt][nt][i] = 0.f;

    const int NC = DD / KC;   // 64

    auto issue = [&](int c, int s) {
#pragma unroll
        for (int i = 0; i < 2; i++) {
            int row = lrow + i * 64;
            uint32_t soff = (uint32_t)(s * 128 * ST + row * ST + lseg * 4) * 4;
            const float* ag = A + (size_t)(bm + row) * DD + c * KC + lseg * 4;
            const float* wg = W + (size_t)(bn + row) * DD + c * KC + lseg * 4;
            cp_async16(aB + soff, ag);
            cp_async16(bB + soff, wg);
        }
        asm volatile("cp.async.commit_group;\n" ::: "memory");
    };

    issue(0, 0);

    for (int c = 0; c < NC; c++) {
        int s = c & 1;
        if (c + 1 < NC) issue(c + 1, s ^ 1);

        if (c + 1 < NC) asm volatile("cp.async.wait_group 1;\n" ::: "memory");
        else            asm volatile("cp.async.wait_group 0;\n" ::: "memory");
        __syncthreads();

        const float* as = As + s * 128 * ST;
        const float* bs = Bs + s * 128 * ST;
#pragma unroll
        for (int ks = 0; ks < 2; ks++) {
            const int k0 = ks * 8;
            uint32_t af[2][4];
            uint32_t bf[8][2];
#pragma unroll
            for (int mt = 0; mt < 2; mt++) {
                int r = wm + mt * 16 + g;
                af[mt][0] = f2tf32(as[r * ST + k0 + t]);
                af[mt][1] = f2tf32(as[(r + 8) * ST + k0 + t]);
                af[mt][2] = f2tf32(as[r * ST + k0 + t + 4]);
                af[mt][3] = f2tf32(as[(r + 8) * ST + k0 + t + 4]);
            }
#pragma unroll
            for (int nt = 0; nt < 8; nt++) {
                int rn = wn + nt * 8 + g;
                bf[nt][0] = f2tf32(bs[rn * ST + k0 + t]);
                bf[nt][1] = f2tf32(bs[rn * ST + k0 + t + 4]);
            }
#pragma unroll
            for (int mt = 0; mt < 2; mt++)
#pragma unroll
                for (int nt = 0; nt < 8; nt++)
                    mma_tf32(acc[mt][nt], af[mt], bf[nt]);
        }
        __syncthreads();
    }

#pragma unroll
    for (int mt = 0; mt < 2; mt++) {
#pragma unroll
        for (int nt = 0; nt < 8; nt++) {
            int m0 = bm + wm + mt * 16 + g;
            int n0 = bn + wn + nt * 8 + 2 * t;
            float b0 = bias[n0];
            float b1 = bias[n0 + 1];
            float2 r0 = make_float2(acc[mt][nt][0] + b0, acc[mt][nt][1] + b1);
            float2 r1 = make_float2(acc[mt][nt][2] + b0, acc[mt][nt][3] + b1);
            if (headMode == 0) {
                *(float2*)(C + (size_t)m0 * DD + n0) = r0;
                *(float2*)(C + (size_t)(m0 + 8) * DD + n0) = r1;
            } else {
                int h = n0 >> 6, d = n0 & 63;
                int b = m0 >> 11, tt0 = m0 & 2047;
                *(float2*)(C + (((size_t)b * HH + h) * TT + tt0) * HD + d) = r0;
                *(float2*)(C + (((size_t)b * HH + h) * TT + tt0 + 8) * HD + d) = r1;
            }
        }
    }
}

// Fused Q/K/V projections: blockIdx.z selects which projection.
__global__ void __launch_bounds__(256) gemm_qkv_kernel(
    const float* __restrict__ q, const float* __restrict__ k,
    const float* __restrict__ v,
    const float* __restrict__ Wq, const float* __restrict__ Wk,
    const float* __restrict__ Wv,
    const float* __restrict__ bq, const float* __restrict__ bk,
    const float* __restrict__ bv,
    float* __restrict__ qh, float* __restrict__ kh, float* __restrict__ vh)
{
    __shared__ float As[2 * 128 * ST];
    __shared__ float Bs[2 * 128 * ST];
    int z = blockIdx.z;
    const float* A = (z == 0) ? q : (z == 1) ? k : v;
    const float* W = (z == 0) ? Wq : (z == 1) ? Wk : Wv;
    const float* bias = (z == 0) ? bq : (z == 1) ? bk : bv;
    float* C = (z == 0) ? qh : (z == 1) ? kh : vh;
    gemm_body(A, W, bias, C, 1, As, Bs);
}

__global__ void __launch_bounds__(256) gemm_o_kernel(
    const float* __restrict__ A, const float* __restrict__ W,
    const float* __restrict__ bias, float* __restrict__ C)
{
    __shared__ float As[2 * 128 * ST];
    __shared__ float Bs[2 * 128 * ST];
    gemm_body(A, W, bias, C, 0, As, Bs);
}

// ===========================================================================
// Flash attention, split-bf16 mma.sync + ldmatrix + cp.async staging.
// Br=128, Bc=64, 8 warps; warp owns m16 x n64 of S (P stays in registers).
// Smem (bytes from base):
//   QH 0      (128 x 144B rows: 64 bf16 data + 8 pad)
//   QL 18432
//   KH 36864  (64 x 144B)
//   KL 46080
//   VH 55296  (64 x 144B, natural [key][hd] layout; trans via ldmatrix)
//   VL 64512
//   Kst 73728 (64 x 272B raw fp32 staging)
//   Vst 91136 (64 x 272B)
// Total 108544 B -> 2 CTAs/SM.
// ===========================================================================
#define QHB 0
#define QLB 18432
#define KHB 36864
#define KLB 46080
#define VHB 55296
#define VLB 64512
#define KSTW 18432   // word offset of K staging
#define VSTW 22784
#define FLASH_SMEM 108544

__global__ void __launch_bounds__(256, 2) flash_tc_kernel(
    const float* __restrict__ Qp, const float* __restrict__ Kp,
    const float* __restrict__ Vp, float* __restrict__ Out)
{
    extern __shared__ uint32_t sm[];
    const uint32_t sb = smem_u32(sm);
    float* sKst = (float*)(sm + KSTW);
    float* sVst = (float*)(sm + VSTW);

    const int tid = threadIdx.x;
    const int wid = tid >> 5;
    const int lane = tid & 31;
    const int g = lane >> 2;
    const int t = lane & 3;
    const int qt = blockIdx.x;
    const int h  = blockIdx.y;
    const int b  = blockIdx.z;

    const float* Qg = Qp + (((size_t)b * HH + h) * TT + qt * 128) * HD;
    const float* Kg = Kp + (((size_t)b * HH + h) * TT) * HD;
    const float* Vg = Vp + (((size_t)b * HH + h) * TT) * HD;

    // ---- Q load + split (once), natural layout, rows stride 36 words ----
#pragma unroll
    for (int it = 0; it < 8; it++) {
        int lin = tid + it * 256;
        int row = lin >> 4;
        int seg = lin & 15;
        float4 v = *(const float4*)(Qg + row * HD + seg * 4);
        v.x *= 0.125f; v.y *= 0.125f; v.z *= 0.125f; v.w *= 0.125f;
        uint32_t h0, l0, h1, l1;
        split2(v.x, v.y, h0, l0);
        split2(v.z, v.w, h1, l1);
        sm[row * 36 + seg * 2]            = h0;
        sm[row * 36 + seg * 2 + 1]        = h1;
        sm[QLB / 4 + row * 36 + seg * 2]     = l0;
        sm[QLB / 4 + row * 36 + seg * 2 + 1] = l1;
    }

    // ---- staging loader ----
    auto issue_kv = [&](int jt) {
#pragma unroll
        for (int it = 0; it < 4; it++) {
            int lin = tid + it * 256;
            int row = lin >> 4;
            int seg = lin & 15;
            uint32_t soff = (uint32_t)(row * 68 + seg * 4) * 4;
            cp_async16(sb + KSTW * 4 + soff,
                       Kg + (size_t)(jt * 64 + row) * HD + seg * 4);
            cp_async16(sb + VSTW * 4 + soff,
                       Vg + (size_t)(jt * 64 + row) * HD + seg * 4);
        }
        asm volatile("cp.async.commit_group;\n" ::: "memory");
    };

    issue_kv(0);

    float o[8][4];
#pragma unroll
    for (int j = 0; j < 8; j++)
#pragma unroll
        for (int i = 0; i < 4; i++) o[j][i] = 0.f;
    float mi0 = -1e30f, mi1 = -1e30f, li0 = 0.f, li1 = 0.f;

    const int mq = wid * 16;
    // ldmatrix lane base addresses (bytes)
    const uint32_t qa_base = sb + QHB + (mq + (lane & 15)) * 144
                           + ((lane >> 4) << 4);
    const uint32_t ka_base = sb + KHB
                           + (((lane >> 4) << 3) + (lane & 7)) * 144
                           + (((lane >> 3) & 1) << 4);
    const uint32_t va_base = sb + VHB
                           + ((((lane >> 3) & 1) << 3) + (lane & 7)) * 144
                           + ((lane >> 4) << 4);

    for (int jt = 0; jt < TT / 64; jt++) {
        asm volatile("cp.async.wait_group 0;\n" ::: "memory");
        __syncthreads();   // staging ready; prev tile's mma done

        // ---- convert K/V tiles from staging -> hi/lo bf16 (natural layout)
#pragma unroll
        for (int it = 0; it < 4; it++) {
            int lin = tid + it * 256;
            int row = lin >> 4;
            int seg = lin & 15;
            float4 kv = *(const float4*)&sKst[row * 68 + seg * 4];
            uint32_t h0, l0, h1, l1;
            split2(kv.x, kv.y, h0, l0);
            split2(kv.z, kv.w, h1, l1);
            sm[KHB / 4 + row * 36 + seg * 2]     = h0;
            sm[KHB / 4 + row * 36 + seg * 2 + 1] = h1;
            sm[KLB / 4 + row * 36 + seg * 2]     = l0;
            sm[KLB / 4 + row * 36 + seg * 2 + 1] = l1;
            float4 vv = *(const float4*)&sVst[row * 68 + seg * 4];
            split2(vv.x, vv.y, h0, l0);
            split2(vv.z, vv.w, h1, l1);
            sm[VHB / 4 + row * 36 + seg * 2]     = h0;
            sm[VHB / 4 + row * 36 + seg * 2 + 1] = h1;
            sm[VLB / 4 + row * 36 + seg * 2]     = l0;
            sm[VLB / 4 + row * 36 + seg * 2 + 1] = l1;
        }
        __syncthreads();   // bf16 tiles ready, staging drained

        if (jt + 1 < TT / 64) issue_kv(jt + 1);   // overlap with mma below

        // ---- S = Qs @ K^T  (split-bf16: Ah*Bh + Ah*Bl + Al*Bh) ----
        float sc[8][4];
#pragma unroll
        for (int j = 0; j < 8; j++)
#pragma unroll
            for (int i = 0; i < 4; i++) sc[j][i] = 0.f;

#pragma unroll
        for (int kb = 0; kb < 4; kb++) {
            uint32_t aH[4], aL[4];
            ldsm4(aH, qa_base + kb * 32);
            ldsm4(aL, qa_base + kb * 32 + (QLB - QHB));
#pragma unroll
            for (int jp = 0; jp < 4; jp++) {
                uint32_t kaddr = ka_base + jp * 16 * 144 + kb * 32;
                uint32_t bH[4], bL[4];
                ldsm4(bH, kaddr);
                ldsm4(bL, kaddr + (KLB - KHB));
                mma_bf16(sc[2 * jp],     aH, &bH[0]);
                mma_bf16(sc[2 * jp],     aH, &bL[0]);
                mma_bf16(sc[2 * jp],     aL, &bH[0]);
                mma_bf16(sc[2 * jp + 1], aH, &bH[2]);
                mma_bf16(sc[2 * jp + 1], aH, &bL[2]);
                mma_bf16(sc[2 * jp + 1], aL, &bH[2]);
            }
        }

        // ---- online softmax (rows g, g+8 of this warp's m16) ----
        float m0 = -1e30f, m1 = -1e30f;
#pragma unroll
        for (int j = 0; j < 8; j++) {
            m0 = fmaxf(m0, fmaxf(sc[j][0], sc[j][1]));
            m1 = fmaxf(m1, fmaxf(sc[j][2], sc[j][3]));
        }
        m0 = fmaxf(m0, __shfl_xor_sync(0xffffffffu, m0, 1));
        m0 = fmaxf(m0, __shfl_xor_sync(0xffffffffu, m0, 2));
        m1 = fmaxf(m1, __shfl_xor_sync(0xffffffffu, m1, 1));
        m1 = fmaxf(m1, __shfl_xor_sync(0xffffffffu, m1, 2));

        float nm0 = fmaxf(mi0, m0), nm1 = fmaxf(mi1, m1);
        float cr0 = __expf(mi0 - nm0), cr1 = __expf(mi1 - nm1);
        mi0 = nm0; mi1 = nm1;

        float rs0 = 0.f, rs1 = 0.f;
#pragma unroll
        for (int j = 0; j < 8; j++) {
            sc[j][0] = __expf(sc[j][0] - nm0);
            sc[j][1] = __expf(sc[j][1] - nm0);
            sc[j][2] = __expf(sc[j][2] - nm1);
            sc[j][3] = __expf(sc[j][3] - nm1);
            rs0 += sc[j][0] + sc[j][1];
            rs1 += sc[j][2] + sc[j][3];
        }
        rs0 += __shfl_xor_sync(0xffffffffu, rs0, 1);
        rs0 += __shfl_xor_sync(0xffffffffu, rs0, 2);
        rs1 += __shfl_xor_sync(0xffffffffu, rs1, 1);
        rs1 += __shfl_xor_sync(0xffffffffu, rs1, 2);
        li0 = li0 * cr0 + rs0;
        li1 = li1 * cr1 + rs1;

#pragma unroll
        for (int j = 0; j < 8; j++) {
            o[j][0] *= cr0; o[j][1] *= cr0;
            o[j][2] *= cr1; o[j][3] *= cr1;
        }

        // ---- O += P @ V  (split-bf16; V B-frags via ldmatrix.trans) ----
#pragma unroll
        for (int kb = 0; kb < 4; kb++) {
            uint32_t aH[4], aL[4];
            split2(sc[2 * kb][0],     sc[2 * kb][1],     aH[0], aL[0]);
            split2(sc[2 * kb][2],     sc[2 * kb][3],     aH[1], aL[1]);
            split2(sc[2 * kb + 1][0], sc[2 * kb + 1][1], aH[2], aL[2]);
            split2(sc[2 * kb + 1][2], sc[2 * kb + 1][3], aH[3], aL[3]);
#pragma unroll
            for (int jp = 0; jp < 4; jp++) {
                uint32_t vaddr = va_base + kb * 16 * 144 + jp * 32;
                uint32_t bH[4], bL[4];
                ldsm4t(bH, vaddr);
                ldsm4t(bL, vaddr + (VLB - VHB));
                mma_bf16(o[2 * jp],     aH, &bH[0]);
                mma_bf16(o[2 * jp],     aH, &bL[0]);
                mma_bf16(o[2 * jp],     aL, &bH[0]);
                mma_bf16(o[2 * jp + 1], aH, &bH[2]);
                mma_bf16(o[2 * jp + 1], aH, &bL[2]);
                mma_bf16(o[2 * jp + 1], aL, &bH[2]);
            }
        }
    }

    // ---- epilogue: normalize, write [B,T,D] ----
    float inv0 = 1.f / li0, inv1 = 1.f / li1;
    int row0 = qt * 128 + mq + g;
#pragma unroll
    for (int j = 0; j < 8; j++) {
        int col = h * HD + j * 8 + 2 * t;
        float2 r0 = make_float2(o[j][0] * inv0, o[j][1] * inv0);
        float2 r1 = make_float2(o[j][2] * inv1, o[j][3] * inv1);
        *(float2*)(Out + ((size_t)b * TT + row0) * DD + col) = r0;
        *(float2*)(Out + ((size_t)b * TT + row0 + 8) * DD + col) = r1;
    }
}

// ---------------------------------------------------------------------------
extern "C" void kernel_launch(void* const* d_in, const int* in_sizes, int n_in,
                              void* d_out, int out_size)
{
    const float* q  = (const float*)d_in[0];
    const float* k  = (const float*)d_in[1];
    const float* v  = (const float*)d_in[2];
    const float* Wq = (const float*)d_in[3];
    const float* bq = (const float*)d_in[4];
    const float* Wk = (const float*)d_in[5];
    const float* bk = (const float*)d_in[6];
    const float* Wv = (const float*)d_in[7];
    const float* bv = (const float*)d_in[8];
    const float* Wo = (const float*)d_in[9];
    const float* bo = (const float*)d_in[10];
    float* out = (float*)d_out;

    float *qh, *kh, *vh, *attn;
    cudaGetSymbolAddress((void**)&qh,   g_qh);
    cudaGetSymbolAddress((void**)&kh,   g_kh);
    cudaGetSymbolAddress((void**)&vh,   g_vh);
    cudaGetSymbolAddress((void**)&attn, g_attn);

    cudaFuncSetAttribute(flash_tc_kernel,
                         cudaFuncAttributeMaxDynamicSharedMemorySize, FLASH_SMEM);

    dim3 qkvgrid(DD / 128, MM / 128, 3);   // (8, 32, 3)
    gemm_qkv_kernel<<<qkvgrid, 256>>>(q, k, v, Wq, Wk, Wv, bq, bk, bv,
                                      qh, kh, vh);

    dim3 fgrid(TT / 128, HH, BB);          // (16, 16, 2)
    flash_tc_kernel<<<fgrid, 256, FLASH_SMEM>>>(qh, kh, vh, attn);

    dim3 ogrid(DD / 128, MM / 128);        // (8, 32)
    gemm_o_kernel<<<ogrid, 256>>>(attn, Wo, bo, out);
}

// round 6
// speedup vs baseline: 3.3158x; 1.0515x over previous
#include <cuda_runtime.h>
#include <cuda_bf16.h>
#include <cstdint>
#include <math.h>

// Problem constants
#define BB 2
#define TT 2048
#define DD 1024
#define HH 16
#define HD 64
#define MM (BB*TT)   // 4096

// Scratch (device globals: allocation-free)
// Pre-split bf16 head tensors, [B,H,T,hd]; Q carries the 1/sqrt(hd) scale.
__device__ __nv_bfloat16 g_qhi[BB*HH*TT*HD];
__device__ __nv_bfloat16 g_qlo[BB*HH*TT*HD];
__device__ __nv_bfloat16 g_khi[BB*HH*TT*HD];
__device__ __nv_bfloat16 g_klo[BB*HH*TT*HD];
__device__ __nv_bfloat16 g_vhi[BB*HH*TT*HD];
__device__ __nv_bfloat16 g_vlo[BB*HH*TT*HD];
__device__ float g_attn[BB*TT*DD];    // [B,T,D] attention output

// ===========================================================================
// Helpers
// ===========================================================================
__device__ __forceinline__ uint32_t smem_u32(const void* p) {
    uint32_t a;
    asm("{ .reg .u64 t; cvta.to.shared.u64 t, %1; cvt.u32.u64 %0, t; }"
        : "=r"(a) : "l"(p));
    return a;
}

__device__ __forceinline__ void cp_async16(uint32_t dst, const void* src) {
    asm volatile("cp.async.cg.shared.global [%0], [%1], 16;\n"
                 :: "r"(dst), "l"(src));
}

__device__ __forceinline__ uint32_t f2tf32(float x) {
    uint32_t r;
    asm("cvt.rna.tf32.f32 %0, %1;" : "=r"(r) : "f"(x));
    return r;
}

__device__ __forceinline__ void mma_tf32(float* c, const uint32_t* a,
                                         const uint32_t* b) {
    asm volatile(
        "mma.sync.aligned.m16n8k8.row.col.f32.tf32.tf32.f32 "
        "{%0,%1,%2,%3}, {%4,%5,%6,%7}, {%8,%9}, {%0,%1,%2,%3};\n"
        : "+f"(c[0]), "+f"(c[1]), "+f"(c[2]), "+f"(c[3])
        : "r"(a[0]), "r"(a[1]), "r"(a[2]), "r"(a[3]),
          "r"(b[0]), "r"(b[1]));
}

__device__ __forceinline__ void mma_bf16(float* c, const uint32_t* a,
                                         const uint32_t* b) {
    asm volatile(
        "mma.sync.aligned.m16n8k16.row.col.f32.bf16.bf16.f32 "
        "{%0,%1,%2,%3}, {%4,%5,%6,%7}, {%8,%9}, {%0,%1,%2,%3};\n"
        : "+f"(c[0]), "+f"(c[1]), "+f"(c[2]), "+f"(c[3])
        : "r"(a[0]), "r"(a[1]), "r"(a[2]), "r"(a[3]),
          "r"(b[0]), "r"(b[1]));
}

__device__ __forceinline__ void ldsm4(uint32_t* r, uint32_t addr) {
    asm volatile(
        "ldmatrix.sync.aligned.m8n8.x4.shared.b16 {%0,%1,%2,%3}, [%4];"
        : "=r"(r[0]), "=r"(r[1]), "=r"(r[2]), "=r"(r[3]) : "r"(addr));
}

__device__ __forceinline__ void ldsm4t(uint32_t* r, uint32_t addr) {
    asm volatile(
        "ldmatrix.sync.aligned.m8n8.x4.trans.shared.b16 {%0,%1,%2,%3}, [%4];"
        : "=r"(r[0]), "=r"(r[1]), "=r"(r[2]), "=r"(r[3]) : "r"(addr));
}

// Split (x,y) into hi/lo bf16x2 words (low half = x).
__device__ __forceinline__ void split2(float x, float y,
                                       uint32_t& hi, uint32_t& lo) {
    __nv_bfloat16 hx = __float2bfloat16(x);
    __nv_bfloat16 hy = __float2bfloat16(y);
    __nv_bfloat16 lx = __float2bfloat16(x - __bfloat162float(hx));
    __nv_bfloat16 ly = __float2bfloat16(y - __bfloat162float(hy));
    __nv_bfloat162 ph = __halves2bfloat162(hx, hy);
    __nv_bfloat162 pl = __halves2bfloat162(lx, ly);
    hi = *(uint32_t*)&ph;
    lo = *(uint32_t*)&pl;
}

// ===========================================================================
// tf32 mma.sync GEMM mainloop (round-3 proven): acc = A @ W^T
// ===========================================================================
#define KC 16
#define ST 20

struct GemmFrag { float acc[2][8][4]; int m0base, n0base; };

__device__ __forceinline__ void gemm_mainloop(
    const float* __restrict__ A, const float* __restrict__ W,
    float* As, float* Bs, GemmFrag& F)
{
    const int tid = threadIdx.x;
    const int wid = tid >> 5;
    const int lane = tid & 31;
    const int g = lane >> 2;
    const int t = lane & 3;
    const int bm = blockIdx.y * 128;
    const int bn = blockIdx.x * 128;
    const int wm = (wid & 3) * 32;
    const int wn = (wid >> 2) * 64;

    const uint32_t aB = smem_u32(As);
    const uint32_t bB = smem_u32(Bs);
    const int lrow = tid >> 2;
    const int lseg = tid & 3;

#pragma unroll
    for (int mt = 0; mt < 2; mt++)
#pragma unroll
        for (int nt = 0; nt < 8; nt++)
#pragma unroll
            for (int i = 0; i < 4; i++) F.acc[mt][nt][i] = 0.f;

    const int NC = DD / KC;   // 64

    auto issue = [&](int c, int s) {
#pragma unroll
        for (int i = 0; i < 2; i++) {
            int row = lrow + i * 64;
            uint32_t soff = (uint32_t)(s * 128 * ST + row * ST + lseg * 4) * 4;
            const float* ag = A + (size_t)(bm + row) * DD + c * KC + lseg * 4;
            const float* wg = W + (size_t)(bn + row) * DD + c * KC + lseg * 4;
            cp_async16(aB + soff, ag);
            cp_async16(bB + soff, wg);
        }
        asm volatile("cp.async.commit_group;\n" ::: "memory");
    };

    issue(0, 0);

    for (int c = 0; c < NC; c++) {
        int s = c & 1;
        if (c + 1 < NC) issue(c + 1, s ^ 1);

        if (c + 1 < NC) asm volatile("cp.async.wait_group 1;\n" ::: "memory");
        else            asm volatile("cp.async.wait_group 0;\n" ::: "memory");
        __syncthreads();

        const float* as = As + s * 128 * ST;
        const float* bs = Bs + s * 128 * ST;
#pragma unroll
        for (int ks = 0; ks < 2; ks++) {
            const int k0 = ks * 8;
            uint32_t af[2][4];
            uint32_t bf[8][2];
#pragma unroll
            for (int mt = 0; mt < 2; mt++) {
                int r = wm + mt * 16 + g;
                af[mt][0] = f2tf32(as[r * ST + k0 + t]);
                af[mt][1] = f2tf32(as[(r + 8) * ST + k0 + t]);
                af[mt][2] = f2tf32(as[r * ST + k0 + t + 4]);
                af[mt][3] = f2tf32(as[(r + 8) * ST + k0 + t + 4]);
            }
#pragma unroll
            for (int nt = 0; nt < 8; nt++) {
                int rn = wn + nt * 8 + g;
                bf[nt][0] = f2tf32(bs[rn * ST + k0 + t]);
                bf[nt][1] = f2tf32(bs[rn * ST + k0 + t + 4]);
            }
#pragma unroll
            for (int mt = 0; mt < 2; mt++)
#pragma unroll
                for (int nt = 0; nt < 8; nt++)
                    mma_tf32(F.acc[mt][nt], af[mt], bf[nt]);
        }
        __syncthreads();
    }
    F.m0base = bm + wm + g;
    F.n0base = bn + wn + 2 * t;
}

// Fused Q/K/V projections, epilogue splits to bf16 hi/lo head tensors.
__global__ void __launch_bounds__(256) gemm_qkv_kernel(
    const float* __restrict__ q, const float* __restrict__ k,
    const float* __restrict__ v,
    const float* __restrict__ Wq, const float* __restrict__ Wk,
    const float* __restrict__ Wv,
    const float* __restrict__ bq, const float* __restrict__ bk,
    const float* __restrict__ bv)
{
    __shared__ float As[2 * 128 * ST];
    __shared__ float Bs[2 * 128 * ST];
    int z = blockIdx.z;
    const float* A = (z == 0) ? q : (z == 1) ? k : v;
    const float* W = (z == 0) ? Wq : (z == 1) ? Wk : Wv;
    const float* bias = (z == 0) ? bq : (z == 1) ? bk : bv;
    __nv_bfloat16* Hi = (z == 0) ? g_qhi : (z == 1) ? g_khi : g_vhi;
    __nv_bfloat16* Lo = (z == 0) ? g_qlo : (z == 1) ? g_klo : g_vlo;
    const float scale = (z == 0) ? 0.125f : 1.0f;

    GemmFrag F;
    gemm_mainloop(A, W, As, Bs, F);

#pragma unroll
    for (int mt = 0; mt < 2; mt++) {
#pragma unroll
        for (int nt = 0; nt < 8; nt++) {
            int m0 = F.m0base + mt * 16;
            int n0 = F.n0base + nt * 8;
            float b0 = bias[n0], b1 = bias[n0 + 1];
            int h = n0 >> 6, d = n0 & 63;
            int b = m0 >> 11, t0 = m0 & 2047;
            size_t idx0 = (((size_t)b * HH + h) * TT + t0) * HD + d;
            uint32_t hi, lo;
            split2((F.acc[mt][nt][0] + b0) * scale,
                   (F.acc[mt][nt][1] + b1) * scale, hi, lo);
            *(uint32_t*)&Hi[idx0] = hi;
            *(uint32_t*)&Lo[idx0] = lo;
            split2((F.acc[mt][nt][2] + b0) * scale,
                   (F.acc[mt][nt][3] + b1) * scale, hi, lo);
            *(uint32_t*)&Hi[idx0 + 8 * HD] = hi;
            *(uint32_t*)&Lo[idx0 + 8 * HD] = lo;
        }
    }
}

// O projection: fp32 epilogue to d_out.
__global__ void __launch_bounds__(256) gemm_o_kernel(
    const float* __restrict__ W, const float* __restrict__ bias,
    float* __restrict__ C)
{
    __shared__ float As[2 * 128 * ST];
    __shared__ float Bs[2 * 128 * ST];
    GemmFrag F;
    gemm_mainloop(g_attn, W, As, Bs, F);

#pragma unroll
    for (int mt = 0; mt < 2; mt++) {
#pragma unroll
        for (int nt = 0; nt < 8; nt++) {
            int m0 = F.m0base + mt * 16;
            int n0 = F.n0base + nt * 8;
            float b0 = bias[n0], b1 = bias[n0 + 1];
            float2 r0 = make_float2(F.acc[mt][nt][0] + b0,
                                    F.acc[mt][nt][1] + b1);
            float2 r1 = make_float2(F.acc[mt][nt][2] + b0,
                                    F.acc[mt][nt][3] + b1);
            *(float2*)(C + (size_t)m0 * DD + n0) = r0;
            *(float2*)(C + (size_t)(m0 + 8) * DD + n0) = r1;
        }
    }
}

// ===========================================================================
// Flash attention: pre-split bf16 inputs, double-buffered cp.async KV,
// ldmatrix fragments, split-bf16 mma. Br=128, Bc=64, 8 warps.
// Smem bytes: QH 0 (128x144), QL 18432, then 2 KV buffers of 36864:
//   per buffer: KH +0, KL +9216, VH +18432, VL +27648 (each 64x144).
// Total 110592 -> 2 CTAs/SM.
// ===========================================================================
#define QLB 18432
#define KVB 36864
#define KVBUF 36864
#define FLASH_SMEM 110592

__global__ void __launch_bounds__(256, 2) flash_tc_kernel(float* __restrict__ Out)
{
    extern __shared__ uint32_t sm[];
    const uint32_t sb = smem_u32(sm);

    const int tid = threadIdx.x;
    const int wid = tid >> 5;
    const int lane = tid & 31;
    const int g = lane >> 2;
    const int t = lane & 3;
    const int qt = blockIdx.x;
    const int h  = blockIdx.y;
    const int b  = blockIdx.z;

    const size_t bh = ((size_t)b * HH + h) * TT * HD;
    const __nv_bfloat16* Qhi = g_qhi + bh + (size_t)qt * 128 * HD;
    const __nv_bfloat16* Qlo = g_qlo + bh + (size_t)qt * 128 * HD;
    const __nv_bfloat16* Khi = g_khi + bh;
    const __nv_bfloat16* Klo = g_klo + bh;
    const __nv_bfloat16* Vhi = g_vhi + bh;
    const __nv_bfloat16* Vlo = g_vlo + bh;

    // ---- Q tiles: 2 arrays x 128 rows x 8 segs ----
#pragma unroll
    for (int it = 0; it < 8; it++) {
        int lin = tid + it * 256;
        int arr = it >> 2;              // 0=hi, 1=lo
        int rem = lin & 1023;
        int row = rem >> 3;
        int seg = rem & 7;
        const __nv_bfloat16* src = (arr == 0 ? Qhi : Qlo) + row * HD + seg * 8;
        cp_async16(sb + arr * QLB + row * 144 + seg * 16, src);
    }

    // ---- KV loader: 4 arrays x 64 rows x 8 segs into buffer s ----
    auto issue_kv = [&](int jt, int s) {
#pragma unroll
        for (int it = 0; it < 8; it++) {
            int lin = tid + it * 256;
            int arr = it >> 1;          // 0=KH 1=KL 2=VH 3=VL
            int rem = lin & 511;
            int row = rem >> 3;
            int seg = rem & 7;
            const __nv_bfloat16* base =
                (arr == 0) ? Khi : (arr == 1) ? Klo : (arr == 2) ? Vhi : Vlo;
            cp_async16(sb + KVB + s * KVBUF + arr * 9216 + row * 144 + seg * 16,
                       base + (size_t)(jt * 64 + row) * HD + seg * 8);
        }
        asm volatile("cp.async.commit_group;\n" ::: "memory");
    };

    issue_kv(0, 0);   // group also contains the Q loads

    float o[8][4];
#pragma unroll
    for (int j = 0; j < 8; j++)
#pragma unroll
        for (int i = 0; i < 4; i++) o[j][i] = 0.f;
    float mi0 = -1e30f, mi1 = -1e30f, li0 = 0.f, li1 = 0.f;

    const int mq = wid * 16;
    const uint32_t qa_base = sb + (mq + (lane & 15)) * 144 + ((lane >> 4) << 4);
    const uint32_t ka_off = (((lane >> 4) << 3) + (lane & 7)) * 144
                          + (((lane >> 3) & 1) << 4);
    const uint32_t va_off = ((((lane >> 3) & 1) << 3) + (lane & 7)) * 144
                          + ((lane >> 4) << 4);

    for (int jt = 0; jt < TT / 64; jt++) {
        asm volatile("cp.async.wait_group 0;\n" ::: "memory");
        __syncthreads();   // KV(jt) visible; all warps done with buffer jt^1

        if (jt + 1 < TT / 64) issue_kv(jt + 1, (jt + 1) & 1);

        const uint32_t kbuf = sb + KVB + (jt & 1) * KVBUF;

        // ---- S = Qs @ K^T  (split-bf16: Ah*Bh + Ah*Bl + Al*Bh) ----
        float sc[8][4];
#pragma unroll
        for (int j = 0; j < 8; j++)
#pragma unroll
            for (int i = 0; i < 4; i++) sc[j][i] = 0.f;

#pragma unroll
        for (int kb = 0; kb < 4; kb++) {
            uint32_t aH[4], aL[4];
            ldsm4(aH, qa_base + kb * 32);
            ldsm4(aL, qa_base + kb * 32 + QLB);
#pragma unroll
            for (int jp = 0; jp < 4; jp++) {
                uint32_t kaddr = kbuf + ka_off + jp * 16 * 144 + kb * 32;
                uint32_t bH[4], bL[4];
                ldsm4(bH, kaddr);
                ldsm4(bL, kaddr + 9216);
                mma_bf16(sc[2 * jp],     aH, &bH[0]);
                mma_bf16(sc[2 * jp],     aH, &bL[0]);
                mma_bf16(sc[2 * jp],     aL, &bH[0]);
                mma_bf16(sc[2 * jp + 1], aH, &bH[2]);
                mma_bf16(sc[2 * jp + 1], aH, &bL[2]);
                mma_bf16(sc[2 * jp + 1], aL, &bH[2]);
            }
        }

        // ---- online softmax (rows g, g+8) ----
        float m0 = -1e30f, m1 = -1e30f;
#pragma unroll
        for (int j = 0; j < 8; j++) {
            m0 = fmaxf(m0, fmaxf(sc[j][0], sc[j][1]));
            m1 = fmaxf(m1, fmaxf(sc[j][2], sc[j][3]));
        }
        m0 = fmaxf(m0, __shfl_xor_sync(0xffffffffu, m0, 1));
        m0 = fmaxf(m0, __shfl_xor_sync(0xffffffffu, m0, 2));
        m1 = fmaxf(m1, __shfl_xor_sync(0xffffffffu, m1, 1));
        m1 = fmaxf(m1, __shfl_xor_sync(0xffffffffu, m1, 2));

        float nm0 = fmaxf(mi0, m0), nm1 = fmaxf(mi1, m1);
        float cr0 = __expf(mi0 - nm0), cr1 = __expf(mi1 - nm1);
        mi0 = nm0; mi1 = nm1;

        float rs0 = 0.f, rs1 = 0.f;
#pragma unroll
        for (int j = 0; j < 8; j++) {
            sc[j][0] = __expf(sc[j][0] - nm0);
            sc[j][1] = __expf(sc[j][1] - nm0);
            sc[j][2] = __expf(sc[j][2] - nm1);
            sc[j][3] = __expf(sc[j][3] - nm1);
            rs0 += sc[j][0] + sc[j][1];
            rs1 += sc[j][2] + sc[j][3];
        }
        rs0 += __shfl_xor_sync(0xffffffffu, rs0, 1);
        rs0 += __shfl_xor_sync(0xffffffffu, rs0, 2);
        rs1 += __shfl_xor_sync(0xffffffffu, rs1, 1);
        rs1 += __shfl_xor_sync(0xffffffffu, rs1, 2);
        li0 = li0 * cr0 + rs0;
        li1 = li1 * cr1 + rs1;

#pragma unroll
        for (int j = 0; j < 8; j++) {
            o[j][0] *= cr0; o[j][1] *= cr0;
            o[j][2] *= cr1; o[j][3] *= cr1;
        }

        // ---- O += P @ V  (split-bf16; V B-frags via ldmatrix.trans) ----
#pragma unroll
        for (int kb = 0; kb < 4; kb++) {
            uint32_t aH[4], aL[4];
            split2(sc[2 * kb][0],     sc[2 * kb][1],     aH[0], aL[0]);
            split2(sc[2 * kb][2],     sc[2 * kb][3],     aH[1], aL[1]);
            split2(sc[2 * kb + 1][0], sc[2 * kb + 1][1], aH[2], aL[2]);
            split2(sc[2 * kb + 1][2], sc[2 * kb + 1][3], aH[3], aL[3]);
#pragma unroll
            for (int jp = 0; jp < 4; jp++) {
                uint32_t vaddr = kbuf + 18432 + va_off + kb * 16 * 144 + jp * 32;
                uint32_t bH[4], bL[4];
                ldsm4t(bH, vaddr);
                ldsm4t(bL, vaddr + 9216);
                mma_bf16(o[2 * jp],     aH, &bH[0]);
                mma_bf16(o[2 * jp],     aH, &bL[0]);
                mma_bf16(o[2 * jp],     aL, &bH[0]);
                mma_bf16(o[2 * jp + 1], aH, &bH[2]);
                mma_bf16(o[2 * jp + 1], aH, &bL[2]);
                mma_bf16(o[2 * jp + 1], aL, &bH[2]);
            }
        }
    }

    // ---- epilogue: normalize, write [B,T,D] ----
    float inv0 = 1.f / li0, inv1 = 1.f / li1;
    int row0 = qt * 128 + mq + g;
#pragma unroll
    for (int j = 0; j < 8; j++) {
        int col = h * HD + j * 8 + 2 * t;
        float2 r0 = make_float2(o[j][0] * inv0, o[j][1] * inv0);
        float2 r1 = make_float2(o[j][2] * inv1, o[j][3] * inv1);
        *(float2*)(Out + ((size_t)b * TT + row0) * DD + col) = r0;
        *(float2*)(Out + ((size_t)b * TT + row0 + 8) * DD + col) = r1;
    }
}

// ---------------------------------------------------------------------------
extern "C" void kernel_launch(void* const* d_in, const int* in_sizes, int n_in,
                              void* d_out, int out_size)
{
    const float* q  = (const float*)d_in[0];
    const float* k  = (const float*)d_in[1];
    const float* v  = (const float*)d_in[2];
    const float* Wq = (const float*)d_in[3];
    const float* bq = (const float*)d_in[4];
    const float* Wk = (const float*)d_in[5];
    const float* bk = (const float*)d_in[6];
    const float* Wv = (const float*)d_in[7];
    const float* bv = (const float*)d_in[8];
    const float* Wo = (const float*)d_in[9];
    const float* bo = (const float*)d_in[10];
    float* out = (float*)d_out;

    float* attn;
    cudaGetSymbolAddress((void**)&attn, g_attn);

    cudaFuncSetAttribute(flash_tc_kernel,
                         cudaFuncAttributeMaxDynamicSharedMemorySize, FLASH_SMEM);

    dim3 qkvgrid(DD / 128, MM / 128, 3);   // (8, 32, 3)
    gemm_qkv_kernel<<<qkvgrid, 256>>>(q, k, v, Wq, Wk, Wv, bq, bk, bv);

    dim3 fgrid(TT / 128, HH, BB);          // (16, 16, 2)
    flash_tc_kernel<<<fgrid, 256, FLASH_SMEM>>>(attn);

    dim3 ogrid(DD / 128, MM / 128);        // (8, 32)
    gemm_o_kernel<<<ogrid, 256>>>(Wo, bo, out);
}